// round 2
// baseline (speedup 1.0000x reference)
#include <cuda_runtime.h>

static constexpr int KC = 5;   // num codebook entries
static constexpr int DC = 10;  // embedding dim (power-expansion degree)

__global__ __launch_bounds__(256) void vq_kernel(
    const float* __restrict__ x, const float* __restrict__ emb,
    float* __restrict__ out, int n)
{
    // Stage the tiny codebook through smem once per block.
    __shared__ float se[KC * DC];
    if (threadIdx.x < KC * DC) se[threadIdx.x] = emb[threadIdx.x];
    __syncthreads();

    // Per-thread register-resident coefficients:
    //   c[k][i] = -2 * emb[k][i]   (exact power-of-2 scale, rounding-equivalent)
    //   s[k]    = ||emb_k||^2
    float c[KC][DC];
    float s[KC];
    #pragma unroll
    for (int k = 0; k < KC; k++) {
        float acc = 0.0f;
        #pragma unroll
        for (int i = 0; i < DC; i++) {
            float e = se[k * DC + i];
            c[k][i] = -2.0f * e;
            acc = fmaf(e, e, acc);
        }
        s[k] = acc;
    }

    const int n4 = n >> 2;
    const float4* __restrict__ x4 = (const float4*)x;
    float4* __restrict__ o4 = (float4*)out;
    const int stride = gridDim.x * blockDim.x;
    const int tid = blockIdx.x * blockDim.x + threadIdx.x;

    for (int i = tid; i < n4; i += stride) {
        float4 v = x4[i];
        float vr[4] = {v.x, v.y, v.z, v.w};
        float res[4];
        #pragma unroll
        for (int e = 0; e < 4; e++) {
            float vv = vr[e];
            float best = 0.0f;
            int bi = 0;
            #pragma unroll
            for (int k = 0; k < KC; k++) {
                // Horner: score_k = s_k - 2 * sum_i emb[k][i] * vv^(i+1)
                float h = c[k][DC - 1];
                #pragma unroll
                for (int j = DC - 2; j >= 0; j--)
                    h = fmaf(h, vv, c[k][j]);
                float score = fmaf(h, vv, s[k]);
                if (k == 0) {
                    best = score;
                } else if (score < best) {   // strict < : first-occurrence argmin
                    best = score;
                    bi = k;
                }
            }
            res[e] = (float)bi;
        }
        o4[i] = make_float4(res[0], res[1], res[2], res[3]);
    }

    // Tail (n not divisible by 4) — same math, scalar.
    for (int i = (n4 << 2) + tid; i < n; i += stride) {
        float vv = x[i];
        float best = 0.0f;
        int bi = 0;
        #pragma unroll
        for (int k = 0; k < KC; k++) {
            float h = c[k][DC - 1];
            #pragma unroll
            for (int j = DC - 2; j >= 0; j--)
                h = fmaf(h, vv, c[k][j]);
            float score = fmaf(h, vv, s[k]);
            if (k == 0) best = score;
            else if (score < best) { best = score; bi = k; }
        }
        out[i] = (float)bi;
    }
}

extern "C" void kernel_launch(void* const* d_in, const int* in_sizes, int n_in,
                              void* d_out, int out_size)
{
    // Inputs per metadata order: x (large), emb (50 elems). Be robust to order.
    const float* x   = (const float*)d_in[0];
    const float* emb = (const float*)d_in[1];
    if (n_in >= 2 && in_sizes[0] == KC * DC && in_sizes[1] != KC * DC) {
        x   = (const float*)d_in[1];
        emb = (const float*)d_in[0];
    }
    float* out = (float*)d_out;
    int n = out_size;

    // Persistent-ish grid: ~3 CTAs/SM at this register footprint.
    int blocks = 148 * 3;
    vq_kernel<<<blocks, 256>>>(x, emb, out, n);
}

// round 3
// speedup vs baseline: 1.1807x; 1.1807x over previous
#include <cuda_runtime.h>

static constexpr int KC = 5;   // codebook entries
static constexpr int DC = 10;  // embedding dim / polynomial degree

// ---- packed f32x2 helpers (Blackwell) ----
__device__ __forceinline__ unsigned long long pack2(float a, float b) {
    unsigned long long r;
    asm("mov.b64 %0, {%1, %2};" : "=l"(r) : "f"(a), "f"(b));
    return r;
}
__device__ __forceinline__ unsigned long long fma2(unsigned long long a,
                                                   unsigned long long b,
                                                   unsigned long long c) {
    unsigned long long d;
    asm("fma.rn.f32x2 %0, %1, %2, %3;" : "=l"(d) : "l"(a), "l"(b), "l"(c));
    return d;
}
__device__ __forceinline__ void unpack2(unsigned long long p, float& lo, float& hi) {
    asm("mov.b64 {%0, %1}, %2;" : "=f"(lo), "=f"(hi) : "l"(p));
}

// argmin over {0, g1..g4}; strict < keeps first occurrence (matches jnp.argmin)
__device__ __forceinline__ float select_idx(float g1, float g2, float g3, float g4) {
    float best = 0.0f, idx = 0.0f;
    idx  = (g1 < best) ? 1.0f : idx;  best = fminf(g1, best);
    idx  = (g2 < best) ? 2.0f : idx;  best = fminf(g2, best);
    idx  = (g3 < best) ? 3.0f : idx;  best = fminf(g3, best);
    idx  = (g4 < best) ? 4.0f : idx;  best = fminf(g4, best);
    return idx;
}

__global__ __launch_bounds__(128, 4) void vq_kernel(
    const float* __restrict__ x, const float* __restrict__ emb,
    float* __restrict__ out, int n)
{
    __shared__ float se[KC * DC];
    if (threadIdx.x < KC * DC) se[threadIdx.x] = emb[threadIdx.x];
    __syncthreads();

    // Difference-polynomial coefficients vs code 0, pre-packed {c,c}:
    //   g_k(v) = (s_k - s_0) + sum_i [-2 (e_k[i] - e_0[i])] v^{i+1}
    float e0[DC];
    float s0 = 0.0f;
    #pragma unroll
    for (int i = 0; i < DC; i++) {
        e0[i] = se[i];
        s0 = fmaf(e0[i], e0[i], s0);
    }
    unsigned long long A[KC - 1][DC];  // A[k][j] = coeff of v^{j+1}, packed
    unsigned long long D[KC - 1];      // packed constant term
    #pragma unroll
    for (int k = 1; k < KC; k++) {
        float sk = 0.0f;
        #pragma unroll
        for (int i = 0; i < DC; i++) {
            float e = se[k * DC + i];
            sk = fmaf(e, e, sk);
            float c = -2.0f * (e - e0[i]);
            A[k - 1][i] = pack2(c, c);
        }
        float d = sk - s0;
        D[k - 1] = pack2(d, d);
    }

    const int n4 = n >> 2;
    const float4* __restrict__ x4 = (const float4*)x;
    float4* __restrict__ o4 = (float4*)out;
    const int stride = gridDim.x * blockDim.x;
    int i = blockIdx.x * blockDim.x + threadIdx.x;

    float4 cur;
    if (i < n4) cur = x4[i];

    for (; i < n4; i += stride) {
        // depth-1 prefetch of next iteration's vector
        int nx = i + stride;
        float4 nxt;
        if (nx < n4) nxt = x4[nx];

        unsigned long long p0 = pack2(cur.x, cur.y);
        unsigned long long p1 = pack2(cur.z, cur.w);

        // 4 packed Horner chains per pair (8 concurrent chains -> good ILP)
        unsigned long long g0[KC - 1], g1[KC - 1];
        #pragma unroll
        for (int k = 0; k < KC - 1; k++) {
            unsigned long long h0 = A[k][DC - 1];
            unsigned long long h1 = A[k][DC - 1];
            #pragma unroll
            for (int j = DC - 2; j >= 0; j--) {
                h0 = fma2(h0, p0, A[k][j]);
                h1 = fma2(h1, p1, A[k][j]);
            }
            g0[k] = fma2(h0, p0, D[k]);
            g1[k] = fma2(h1, p1, D[k]);
        }

        float a1, b1, a2, b2, a3, b3, a4, b4;
        unpack2(g0[0], a1, b1); unpack2(g0[1], a2, b2);
        unpack2(g0[2], a3, b3); unpack2(g0[3], a4, b4);
        float4 r;
        r.x = select_idx(a1, a2, a3, a4);
        r.y = select_idx(b1, b2, b3, b4);
        unpack2(g1[0], a1, b1); unpack2(g1[1], a2, b2);
        unpack2(g1[2], a3, b3); unpack2(g1[3], a4, b4);
        r.z = select_idx(a1, a2, a3, a4);
        r.w = select_idx(b1, b2, b3, b4);

        o4[i] = r;
        cur = nxt;
    }

    // Scalar tail (n % 4) — recompute scalar diff coefficients from smem.
    for (int t = (n4 << 2) + blockIdx.x * blockDim.x + threadIdx.x; t < n; t += stride) {
        float v = x[t];
        float g[KC - 1];
        #pragma unroll
        for (int k = 1; k < KC; k++) {
            float sk = 0.0f, s0t = 0.0f;
            float h = -2.0f * (se[k * DC + DC - 1] - se[DC - 1]);
            #pragma unroll
            for (int j = DC - 2; j >= 0; j--)
                h = fmaf(h, v, -2.0f * (se[k * DC + j] - se[j]));
            #pragma unroll
            for (int ii = 0; ii < DC; ii++) {
                float ek = se[k * DC + ii], e0t = se[ii];
                sk = fmaf(ek, ek, sk);
                s0t = fmaf(e0t, e0t, s0t);
            }
            g[k - 1] = fmaf(h, v, sk - s0t);
        }
        out[t] = select_idx(g[0], g[1], g[2], g[3]);
    }
}

extern "C" void kernel_launch(void* const* d_in, const int* in_sizes, int n_in,
                              void* d_out, int out_size)
{
    const float* x   = (const float*)d_in[0];
    const float* emb = (const float*)d_in[1];
    if (n_in >= 2 && in_sizes[0] == KC * DC && in_sizes[1] != KC * DC) {
        x   = (const float*)d_in[1];
        emb = (const float*)d_in[0];
    }
    float* out = (float*)d_out;
    int n = out_size;

    int blocks = 148 * 8;  // grid-stride, ~14 iterations/thread
    vq_kernel<<<blocks, 128>>>(x, emb, out, n);
}

// round 6
// speedup vs baseline: 1.6336x; 1.3836x over previous
#include <cuda_runtime.h>

static constexpr int KC = 5;
static constexpr int DC = 10;
static constexpr int NBINS = 16384;
static constexpr float EPS_MARGIN = 2e-4f;

__device__ unsigned char g_lut[NBINS];

// strict < keeps first occurrence (matches jnp.argmin); scores = {0, g1..g4}
__device__ __forceinline__ float select_idx(float g1, float g2, float g3, float g4) {
    float best = 0.0f, idx = 0.0f;
    idx  = (g1 < best) ? 1.0f : idx;  best = fminf(g1, best);
    idx  = (g2 < best) ? 2.0f : idx;  best = fminf(g2, best);
    idx  = (g3 < best) ? 3.0f : idx;  best = fminf(g3, best);
    idx  = (g4 < best) ? 4.0f : idx;  best = fminf(g4, best);
    return idx;
}

// ---------------- Kernel A: LUT builder ----------------
__global__ __launch_bounds__(256) void vq_build_lut(const float* __restrict__ emb)
{
    int bin = blockIdx.x * blockDim.x + threadIdx.x;
    if (bin >= NBINS) return;

    // Difference-poly coefficients vs code 0 (EXACT same expressions as fallback)
    float c[KC - 1][DC], d[KC - 1];
    {
        float e0[DC], s0 = 0.0f;
        #pragma unroll
        for (int i = 0; i < DC; i++) { e0[i] = emb[i]; s0 = fmaf(e0[i], e0[i], s0); }
        #pragma unroll
        for (int k = 1; k < KC; k++) {
            float sk = 0.0f;
            #pragma unroll
            for (int i = 0; i < DC; i++) {
                float e = emb[k * DC + i];
                sk = fmaf(e, e, sk);
                c[k - 1][i] = -2.0f * (e - e0[i]);
            }
            d[k - 1] = sk - s0;
        }
    }

    const float offs[7] = {-0.25f, 0.0f, 0.25f, 0.5f, 0.75f, 1.0f, 1.25f};
    int w0 = -1;
    bool ok = true;
    #pragma unroll
    for (int t = 0; t < 7; t++) {
        float v = ((float)bin + offs[t]) * (1.0f / (float)NBINS);
        float sc[KC];
        sc[0] = 0.0f;
        #pragma unroll
        for (int k = 0; k < KC - 1; k++) {
            float h = c[k][DC - 1];
            #pragma unroll
            for (int j = DC - 2; j >= 0; j--) h = fmaf(h, v, c[k][j]);
            sc[k + 1] = fmaf(h, v, d[k]);
        }
        int w = 0; float best = sc[0];
        #pragma unroll
        for (int k = 1; k < KC; k++) if (sc[k] < best) { best = sc[k]; w = k; }
        float second = 3.4e38f;
        #pragma unroll
        for (int k = 0; k < KC; k++) if (k != w) second = fminf(second, sc[k]);
        if (t == 0) w0 = w;
        ok = ok && (w == w0) && (second - best > EPS_MARGIN);
    }
    g_lut[bin] = ok ? (unsigned char)w0 : (unsigned char)255;
}

// ---------------- Kernel B: LUT-mapped quantize ----------------
__global__ __launch_bounds__(256) void vq_map(
    const float* __restrict__ x, const float* __restrict__ emb,
    float* __restrict__ out, int n)
{
    __shared__ unsigned char slut[NBINS];
    __shared__ float scoef[(KC - 1) * DC + (KC - 1)];  // 40 coeffs + 4 consts

    // Cooperative LUT copy (gmem -> smem), 16-byte chunks
    {
        const uint4* src = (const uint4*)g_lut;
        uint4* dst = (uint4*)slut;
        for (int i = threadIdx.x; i < NBINS / 16; i += blockDim.x) dst[i] = src[i];
    }
    // Coefficients (same expressions as builder)
    if (threadIdx.x < (KC - 1) * DC) {
        int k = threadIdx.x / DC + 1, j = threadIdx.x % DC;
        scoef[threadIdx.x] = -2.0f * (emb[k * DC + j] - emb[j]);
    } else if (threadIdx.x < (KC - 1) * DC + (KC - 1)) {
        int k = threadIdx.x - (KC - 1) * DC + 1;
        float sk = 0.0f, s0 = 0.0f;
        #pragma unroll
        for (int i = 0; i < DC; i++) {
            float ek = emb[k * DC + i], e0 = emb[i];
            sk = fmaf(ek, ek, sk);
            s0 = fmaf(e0, e0, s0);
        }
        scoef[threadIdx.x] = sk - s0;
    }
    __syncthreads();

    auto fallback = [&](float v) -> float {
        float g[KC - 1];
        #pragma unroll
        for (int k = 0; k < KC - 1; k++) {
            float h = scoef[k * DC + DC - 1];
            #pragma unroll
            for (int j = DC - 2; j >= 0; j--) h = fmaf(h, v, scoef[k * DC + j]);
            g[k] = fmaf(h, v, scoef[(KC - 1) * DC + k]);
        }
        return select_idx(g[0], g[1], g[2], g[3]);
    };

    const int n4 = n >> 2;
    const float4* __restrict__ x4 = (const float4*)x;
    float4* __restrict__ o4 = (float4*)out;
    const int stride = gridDim.x * blockDim.x;

    for (int i = blockIdx.x * blockDim.x + threadIdx.x; i < n4; i += stride) {
        float4 v = x4[i];
        float vr[4] = {v.x, v.y, v.z, v.w};
        float res[4];
        unsigned code[4];
        bool any_slow = false;
        #pragma unroll
        for (int e = 0; e < 4; e++) {
            float t = vr[e] * (float)NBINS;
            int b = (int)t;                       // trunc toward zero
            unsigned ub = (unsigned)b;
            unsigned cb = (ub < (unsigned)NBINS) ? (unsigned)slut[ub] : 255u;
            code[e] = cb;
            res[e] = (float)cb;
            any_slow = any_slow || (cb == 255u);
        }
        if (any_slow) {                            // rare: exact polynomial path
            #pragma unroll
            for (int e = 0; e < 4; e++)
                if (code[e] == 255u) res[e] = fallback(vr[e]);
        }
        o4[i] = make_float4(res[0], res[1], res[2], res[3]);
    }

    // Scalar tail: always exact fallback (<= 3 elements total)
    for (int t = (n4 << 2) + blockIdx.x * blockDim.x + threadIdx.x; t < n; t += stride)
        out[t] = fallback(x[t]);
}

extern "C" void kernel_launch(void* const* d_in, const int* in_sizes, int n_in,
                              void* d_out, int out_size)
{
    const float* x   = (const float*)d_in[0];
    const float* emb = (const float*)d_in[1];
    if (n_in >= 2 && in_sizes[0] == KC * DC && in_sizes[1] != KC * DC) {
        x   = (const float*)d_in[1];
        emb = (const float*)d_in[0];
    }
    float* out = (float*)d_out;
    int n = out_size;

    vq_build_lut<<<NBINS / 256, 256>>>(emb);
    vq_map<<<592, 256>>>(x, emb, out, n);   // 4 CTAs/SM persistent, ~14 iters/thread
}